// round 9
// baseline (speedup 1.0000x reference)
#include <cuda_runtime.h>
#include <cuda_bf16.h>
#include <cstdint>
#include <math.h>

// Problem constants
#define NB     64
#define NOBJ   5
#define NIMG   (NB*NOBJ)        // 320 images per state
#define CIN    3
#define HI     64
#define WI     96
#define HO     32
#define WO     48
#define NPOS   (HO*WO)          // 1536
#define COUT   128
#define PP     4
#define NT     (NB*NOBJ*NOBJ)   // 1600

#define NTHR   256              // 16x16 grid of 2x3 output blocks
#define NWARP  (NTHR/32)

#define IMG_ELEMS (CIN*HI*WI)               // 18432
#define IMG_BF16_BYTES (IMG_ELEMS*2)        // 36864
// smem: 2 bf16 image buffers + planes [5][1536] of bf16x2 (A,B)
#define PL_U32_ELEMS (5*NPOS)               // 7680 u32 = 30720 B
#define SMEM_BYTES (2*IMG_BF16_BYTES + PL_U32_ELEMS*4)   // 104448 B

// Static scratch
__device__ __nv_bfloat16 g_imgs[(size_t)2 * NIMG * IMG_ELEMS];  // 23.6 MB
__device__ float g_S[(size_t)2 * NT * COUT];                    // 3.2 MB

// ---- TMA bulk + mbarrier helpers -------------------------------------------
__device__ __forceinline__ void mbar_init(uint32_t addr, uint32_t count) {
    asm volatile("mbarrier.init.shared.b64 [%0], %1;" :: "r"(addr), "r"(count) : "memory");
}
__device__ __forceinline__ void mbar_expect_tx(uint32_t addr, uint32_t bytes) {
    asm volatile("mbarrier.arrive.expect_tx.shared.b64 _, [%0], %1;"
                 :: "r"(addr), "r"(bytes) : "memory");
}
__device__ __forceinline__ void tma_bulk_g2s(uint32_t dst, const void* src,
                                             uint32_t bytes, uint32_t mbar) {
    asm volatile("cp.async.bulk.shared::cta.global.mbarrier::complete_tx::bytes "
                 "[%0], [%1], %2, [%3];"
                 :: "r"(dst), "l"(src), "r"(bytes), "r"(mbar) : "memory");
}
__device__ __forceinline__ void mbar_wait(uint32_t mbar, uint32_t parity) {
    uint32_t done;
    asm volatile(
        "{\n\t.reg .pred p;\n\t"
        "mbarrier.try_wait.parity.acquire.cta.shared::cta.b64 p, [%1], %2;\n\t"
        "selp.b32 %0, 1, 0, p;\n\t}"
        : "=r"(done) : "r"(mbar), "r"(parity) : "memory");
    if (!done) {
        asm volatile(
            "{\n\t.reg .pred P1;\n\t"
            "WAIT_LOOP_%=:\n\t"
            "mbarrier.try_wait.parity.acquire.cta.shared::cta.b64 P1, [%0], %1, 0x989680;\n\t"
            "@P1 bra.uni WAIT_DONE_%=;\n\t"
            "bra.uni WAIT_LOOP_%=;\n\t"
            "WAIT_DONE_%=:\n\t}"
            :: "r"(mbar), "r"(parity) : "memory");
    }
}

// exact bf16x2 -> 2x f32 via bit ops (alu pipe, dual-issues with FFMA)
__device__ __forceinline__ void bf2f(uint32_t u, float& lo, float& hi) {
    lo = __uint_as_float(u << 16);
    hi = __uint_as_float(u & 0xFFFF0000u);
}

// ---------------------------------------------------------------------------
// fp32 -> bf16 image conversion (both states)
// ---------------------------------------------------------------------------
#define N4PS (NIMG*IMG_ELEMS/4)   // float4s per state: 1,474,560
__global__ __launch_bounds__(256)
void cvt_kernel(const float* __restrict__ a, const float* __restrict__ bsrc,
                __nv_bfloat16* __restrict__ out)
{
    int i = blockIdx.x * blockDim.x + threadIdx.x;
    if (i >= 2*N4PS) return;
    const float* src = (i < N4PS) ? a : bsrc;
    int j = (i < N4PS) ? i : i - N4PS;
    float4 v = ((const float4*)src)[j];
    union { __nv_bfloat162 h2[2]; uint2 u; } cv;
    cv.h2[0] = __floats2bfloat162_rn(v.x, v.y);
    cv.h2[1] = __floats2bfloat162_rn(v.z, v.w);
    ((uint2*)out)[i] = cv.u;
}

// ---------------------------------------------------------------------------
// Fused conv + pairwise-combine. CTA = (channel g, batch b, state z).
// conv(concat(img_i,img_j), W) = conv(img_i, W_a) + conv(img_j, W_b).
// bf16 images via TMA bulk (double buffered); 2 CTAs/SM overlap TMA & compute.
// Each thread computes a 2x3 output block.
// ---------------------------------------------------------------------------
__global__ __launch_bounds__(NTHR, 2)
void fused_kernel(const __nv_bfloat16* __restrict__ gimgs,
                  const float* __restrict__ conv_w,   // [128][6][3][3]
                  const float* __restrict__ conv_b,   // [128]
                  float* __restrict__ S)              // [2][1600][128]
{
    extern __shared__ __align__(16) char smc[];
    const __nv_bfloat16* buf[2] = { (const __nv_bfloat16*)smc,
                                    (const __nv_bfloat16*)(smc + IMG_BF16_BYTES) };
    uint32_t* pl = (uint32_t*)(smc + 2*IMG_BF16_BYTES);   // [5][1536] bf16x2(A,B)
    __shared__ float red[25][NWARP];
    __shared__ __align__(8) unsigned long long mbar_store[2];

    const int g   = blockIdx.x;     // channel 0..127
    const int b   = blockIdx.y;     // batch 0..63
    const int z   = blockIdx.z;     // state 0..1
    const int tid = threadIdx.x;

    uint32_t buf_u32[2];
    buf_u32[0] = (uint32_t)__cvta_generic_to_shared(buf[0]);
    buf_u32[1] = (uint32_t)__cvta_generic_to_shared(buf[1]);
    uint32_t mbar_u32 = (uint32_t)__cvta_generic_to_shared(mbar_store);

    // Filter halves in registers (uniform -> broadcast loads)
    float wA[27], wB[27];
    #pragma unroll
    for (int t = 0; t < 27; t++) {
        int ic = t / 9, kk = t % 9;
        wA[t] = conv_w[(g*6 +     ic)*9 + kk];
        wB[t] = conv_w[(g*6 + 3 + ic)*9 + kk];
    }
    const float bias = conv_b[g];

    const __nv_bfloat16* imgs = gimgs + ((size_t)(z*NB + b) * NOBJ) * IMG_ELEMS;

    if (tid == 0) {
        mbar_init(mbar_u32 + 0, 1);
        mbar_init(mbar_u32 + 8, 1);
    }
    __syncthreads();
    if (tid == 0) {
        mbar_expect_tx(mbar_u32 + 0, IMG_BF16_BYTES);
        tma_bulk_g2s(buf_u32[0], imgs + 0*IMG_ELEMS, IMG_BF16_BYTES, mbar_u32 + 0);
        mbar_expect_tx(mbar_u32 + 8, IMG_BF16_BYTES);
        tma_bulk_g2s(buf_u32[1], imgs + 1*IMG_ELEMS, IMG_BF16_BYTES, mbar_u32 + 8);
    }

    // 2x3 output block: 16x16 thread grid. out rows 2by..2by+1, cols 3bx..3bx+2
    const int by = tid >> 4, bx = tid & 15;
    const int iy = 4*by;            // input rows iy..iy+4
    const int ix = 6*bx;            // input cols ix..ix+6 (col 96 = SAME pad)
    const bool right_edge = (bx == 15);
    const bool bot_edge   = (by == 15);

    for (int i = 0; i < 5; i++) {
        mbar_wait(mbar_u32 + 8*(i & 1), (i >> 1) & 1);   // image i ready

        const __nv_bfloat16* sb = buf[i & 1];

        float accA[6], accB[6];     // p = dy*3 + oxk
        #pragma unroll
        for (int p = 0; p < 6; p++) { accA[p] = 0.f; accB[p] = 0.f; }

        #pragma unroll
        for (int c = 0; c < 3; c++) {
            #pragma unroll
            for (int r = 0; r < 5; r++) {
                float v[8];
                if (bot_edge && r == 4) {
                    #pragma unroll
                    for (int k = 0; k < 8; k++) v[k] = 0.f;
                } else {
                    const uint32_t* row =
                        (const uint32_t*)(sb + (c*HI + iy + r)*WI + ix);
                    uint32_t u0 = row[0], u1 = row[1], u2 = row[2], u3 = row[3];
                    bf2f(u0, v[0], v[1]);
                    bf2f(u1, v[2], v[3]);
                    bf2f(u2, v[4], v[5]);
                    bf2f(u3, v[6], v[7]);
                    if (right_edge) v[6] = 0.f;   // col 96 SAME pad
                }

                if (r < 3) {                      // top out-row, ky = r
                    #pragma unroll
                    for (int kx = 0; kx < 3; kx++) {
                        float wa = wA[c*9 + r*3 + kx], wb = wB[c*9 + r*3 + kx];
                        #pragma unroll
                        for (int ox = 0; ox < 3; ox++) {
                            accA[ox] = fmaf(wa, v[2*ox + kx], accA[ox]);
                            accB[ox] = fmaf(wb, v[2*ox + kx], accB[ox]);
                        }
                    }
                }
                if (r >= 2) {                     // bottom out-row, ky = r-2
                    #pragma unroll
                    for (int kx = 0; kx < 3; kx++) {
                        float wa = wA[c*9 + (r-2)*3 + kx], wb = wB[c*9 + (r-2)*3 + kx];
                        #pragma unroll
                        for (int ox = 0; ox < 3; ox++) {
                            accA[3+ox] = fmaf(wa, v[2*ox + kx], accA[3+ox]);
                            accB[3+ox] = fmaf(wb, v[2*ox + kx], accB[3+ox]);
                        }
                    }
                }
            }
        }

        // Store 6 positions as bf16x2 (A+bias, B)
        #pragma unroll
        for (int p = 0; p < 6; p++) {
            int dy = p / 3, oxk = p % 3;
            int pos = (2*by + dy)*WO + 3*bx + oxk;
            union { __nv_bfloat162 h2; uint32_t u; } cv;
            cv.h2 = __floats2bfloat162_rn(accA[p] + bias, accB[p]);
            pl[i*NPOS + pos] = cv.u;
        }

        __syncthreads();                 // all threads done with buf[i&1]
        if (i < 3 && tid == 0) {         // refill with image i+2
            uint32_t m = mbar_u32 + 8*(i & 1);
            mbar_expect_tx(m, IMG_BF16_BYTES);
            tma_bulk_g2s(buf_u32[i & 1], imgs + (i+2)*IMG_ELEMS, IMG_BF16_BYTES, m);
        }
    }
    __syncthreads();                     // all planes visible

    // Combine: 25 pairs, per-thread accumulation over 6 positions
    float acc[25];
    #pragma unroll
    for (int q = 0; q < 25; q++) acc[q] = 0.f;

    #pragma unroll
    for (int k = 0; k < 6; k++) {
        int pos = tid + k*NTHR;
        float A[5], B[5];
        #pragma unroll
        for (int i = 0; i < 5; i++)
            bf2f(pl[i*NPOS + pos], A[i], B[i]);
        #pragma unroll
        for (int i = 0; i < 5; i++)
            #pragma unroll
            for (int j = 0; j < 5; j++)
                acc[i*5 + j] += fmaxf(A[i] + B[j], 0.f);
    }

    // Warp reduce then cross-warp
    const int lane = tid & 31, wid = tid >> 5;
    #pragma unroll
    for (int q = 0; q < 25; q++) {
        float s = acc[q];
        #pragma unroll
        for (int off = 16; off; off >>= 1)
            s += __shfl_xor_sync(0xFFFFFFFFu, s, off);
        if (lane == 0) red[q][wid] = s;
    }
    __syncthreads();

    if (tid < 25) {
        float s = 0.f;
        #pragma unroll
        for (int k = 0; k < NWARP; k++) s += red[tid][k];
        S[((size_t)z*NT + b*25 + tid)*COUT + g] = s;
    }
}

// ---------------------------------------------------------------------------
// logits over BOTH states (3200 tuples): warp per tuple.
// ---------------------------------------------------------------------------
__global__ __launch_bounds__(256)
void logits_kernel(const float* __restrict__ S,    // [3200][128]
                   const float* __restrict__ w2,   // [4][32]
                   const float* __restrict__ b2,   // [4]
                   const float* __restrict__ temp,
                   float* __restrict__ out)        // [3200][4] = preds|preds_next
{
    const int lane = threadIdx.x & 31;
    const int t = blockIdx.x * 8 + (threadIdx.x >> 5);
    if (t >= 2*NT) return;

    float s[4];
    #pragma unroll
    for (int p = 0; p < 4; p++)
        s[p] = S[(size_t)t*COUT + p*32 + lane] * w2[p*32 + lane];
    #pragma unroll
    for (int off = 16; off; off >>= 1)
        #pragma unroll
        for (int p = 0; p < 4; p++)
            s[p] += __shfl_xor_sync(0xFFFFFFFFu, s[p], off);

    if (lane < 4) {
        float invT = 1.0f / (*temp);
        float logit = s[lane] * (1.0f / (float)NPOS) + b2[lane];
        out[t*4 + lane] = 1.0f / (1.0f + expf(-logit * invT));
    }
}

// adj[b][t] = (t / 25 == b)
__global__ void adj_kernel(float* __restrict__ out)
{
    int idx = blockIdx.x * blockDim.x + threadIdx.x;
    if (idx >= NB * NT) return;
    int b = idx / NT;
    int t = idx % NT;
    out[idx] = (t / (NOBJ*NOBJ) == b) ? 1.0f : 0.0f;
}

// ---------------------------------------------------------------------------
extern "C" void kernel_launch(void* const* d_in, const int* in_sizes, int n_in,
                              void* d_out, int out_size)
{
    const float* state      = (const float*)d_in[0];
    const float* state_next = (const float*)d_in[1];
    const float* conv_w     = (const float*)d_in[2];
    const float* conv_b     = (const float*)d_in[3];
    const float* w2         = (const float*)d_in[4];
    const float* b2         = (const float*)d_in[5];
    // d_in[6] = n_obj (constant NOBJ), d_in[7] = temp
    const float* temp       = (const float*)d_in[7];
    float* out = (float*)d_out;

    __nv_bfloat16* imgs; cudaGetSymbolAddress((void**)&imgs, g_imgs);
    float* S;            cudaGetSymbolAddress((void**)&S, g_S);

    cudaFuncSetAttribute(fused_kernel, cudaFuncAttributeMaxDynamicSharedMemorySize,
                         SMEM_BYTES);

    // 1) convert both states' images to bf16
    cvt_kernel<<<(2*N4PS + 255)/256, 256>>>(state, state_next, imgs);

    // 2) fused conv+combine for both states, grid (channel, batch, state)
    fused_kernel<<<dim3(COUT, NB, 2), NTHR, SMEM_BYTES>>>(imgs, conv_w, conv_b, S);

    // 3) logits for both states (out is contiguous preds|preds_next)
    logits_kernel<<<(2*NT + 7)/8, 256>>>(S, w2, b2, temp, out);

    // 4) adjacency
    adj_kernel<<<(NB*NT + 255)/256, 256>>>(out + 2*NT*PP);
}

// round 10
// speedup vs baseline: 1.0234x; 1.0234x over previous
#include <cuda_runtime.h>
#include <cuda_bf16.h>
#include <cstdint>
#include <math.h>

// Problem constants
#define NB     64
#define NOBJ   5
#define CIN    3
#define HI     64
#define WI     96
#define HO     32
#define WO     48
#define NPOS   (HO*WO)          // 1536
#define COUT   128
#define PP     4
#define NT     (NB*NOBJ*NOBJ)   // 1600

#define NTHR   384              // 12 warps; 16x24 grid of 2x2 output blocks
#define NWARP  (NTHR/32)

// Unpadded f32 image buffer: [3][64][96] = 73728 B (TMA bulk)
#define IMG_ELEMS (CIN*HI*WI)                  // 18432
#define IMG_BYTES (IMG_ELEMS*4)
// Planes (bf16): [5 img][1536 pos][4] packed (A0,A1),(B0,B1)
#define PL_BF16_ELEMS (5*NPOS*4)
#define SMEM_BYTES (2*IMG_BYTES + PL_BF16_ELEMS*2)   // 208896 B

__device__ float g_S[(size_t)2 * NT * COUT];   // [2][1600][128]

typedef unsigned long long u64;

// ---- packed f32x2 helpers ---------------------------------------------------
__device__ __forceinline__ u64 pack2(float lo, float hi) {
    u64 r; asm("mov.b64 %0, {%1, %2};" : "=l"(r) : "f"(lo), "f"(hi)); return r;
}
__device__ __forceinline__ float2 unpack2(u64 v) {
    float2 f; asm("mov.b64 {%0, %1}, %2;" : "=f"(f.x), "=f"(f.y) : "l"(v)); return f;
}
__device__ __forceinline__ u64 fma2(u64 a, u64 b, u64 c) {
    u64 d; asm("fma.rn.f32x2 %0, %1, %2, %3;" : "=l"(d) : "l"(a), "l"(b), "l"(c)); return d;
}
__device__ __forceinline__ u64 add2(u64 a, u64 b) {
    u64 d; asm("add.rn.f32x2 %0, %1, %2;" : "=l"(d) : "l"(a), "l"(b)); return d;
}

// ---- TMA bulk + mbarrier helpers -------------------------------------------
__device__ __forceinline__ void mbar_init(uint32_t addr, uint32_t count) {
    asm volatile("mbarrier.init.shared.b64 [%0], %1;" :: "r"(addr), "r"(count) : "memory");
}
__device__ __forceinline__ void mbar_expect_tx(uint32_t addr, uint32_t bytes) {
    asm volatile("mbarrier.arrive.expect_tx.shared.b64 _, [%0], %1;"
                 :: "r"(addr), "r"(bytes) : "memory");
}
__device__ __forceinline__ void tma_bulk_g2s(uint32_t dst, const void* src,
                                             uint32_t bytes, uint32_t mbar) {
    asm volatile("cp.async.bulk.shared::cta.global.mbarrier::complete_tx::bytes "
                 "[%0], [%1], %2, [%3];"
                 :: "r"(dst), "l"(src), "r"(bytes), "r"(mbar) : "memory");
}
__device__ __forceinline__ void mbar_wait(uint32_t mbar, uint32_t parity) {
    uint32_t done;
    asm volatile(
        "{\n\t.reg .pred p;\n\t"
        "mbarrier.try_wait.parity.acquire.cta.shared::cta.b64 p, [%1], %2;\n\t"
        "selp.b32 %0, 1, 0, p;\n\t}"
        : "=r"(done) : "r"(mbar), "r"(parity) : "memory");
    if (!done) {
        asm volatile(
            "{\n\t.reg .pred P1;\n\t"
            "WAIT_LOOP_%=:\n\t"
            "mbarrier.try_wait.parity.acquire.cta.shared::cta.b64 P1, [%0], %1, 0x989680;\n\t"
            "@P1 bra.uni WAIT_DONE_%=;\n\t"
            "bra.uni WAIT_LOOP_%=;\n\t"
            "WAIT_DONE_%=:\n\t}"
            :: "r"(mbar), "r"(parity) : "memory");
    }
}

// ---------------------------------------------------------------------------
// Fused conv + pairwise-combine, FFMA2 mainloop, both states in one launch.
// CTA = (channel-pair g, batch b, state z). Channels c0=2g, c1=2g+1.
// conv(concat(img_i,img_j), W) = conv(img_i, W_a) + conv(img_j, W_b).
// ---------------------------------------------------------------------------
__global__ __launch_bounds__(NTHR, 1)
void fused_kernel(const float* __restrict__ input0,  // state  [320][3][64][96]
                  const float* __restrict__ input1,  // state_next
                  const float* __restrict__ conv_w,  // [128][6][3][3]
                  const float* __restrict__ conv_b,  // [128]
                  float* __restrict__ S)             // [2][1600][128]
{
    extern __shared__ __align__(16) float sm[];
    float* buf[2] = { sm, sm + IMG_ELEMS };
    __nv_bfloat16* pl = (__nv_bfloat16*)(sm + 2*IMG_ELEMS);
    __shared__ float red[50][NWARP];
    __shared__ __align__(8) unsigned long long mbar_store[2];

    const int g   = blockIdx.x;     // 0..63
    const int b   = blockIdx.y;     // 0..63
    const int z   = blockIdx.z;     // 0..1
    const int tid = threadIdx.x;
    const int c0  = g*2, c1 = g*2 + 1;

    uint32_t buf_u32[2];
    buf_u32[0] = (uint32_t)__cvta_generic_to_shared(buf[0]);
    buf_u32[1] = (uint32_t)__cvta_generic_to_shared(buf[1]);
    uint32_t mbar_u32 = (uint32_t)__cvta_generic_to_shared(mbar_store);

    // Packed filter pairs: wp01[t] = (W_a(c0)[t], W_b(c0)[t]); wp23 for c1.
    u64 wp01[27], wp23[27];
    #pragma unroll
    for (int t = 0; t < 27; t++) {
        int ic = t / 9, kk = t % 9;
        wp01[t] = pack2(conv_w[(c0*6 + ic)*9 + kk], conv_w[(c0*6 + 3 + ic)*9 + kk]);
        wp23[t] = pack2(conv_w[(c1*6 + ic)*9 + kk], conv_w[(c1*6 + 3 + ic)*9 + kk]);
    }
    const float bias0 = conv_b[c0];
    const float bias1 = conv_b[c1];

    const float* imgs = (z ? input1 : input0) + (size_t)b * NOBJ * IMG_ELEMS;

    if (tid == 0) {
        mbar_init(mbar_u32 + 0, 1);
        mbar_init(mbar_u32 + 8, 1);
    }
    __syncthreads();
    if (tid == 0) {
        mbar_expect_tx(mbar_u32 + 0, IMG_BYTES);
        tma_bulk_g2s(buf_u32[0], imgs + 0*IMG_ELEMS, IMG_BYTES, mbar_u32 + 0);
        mbar_expect_tx(mbar_u32 + 8, IMG_BYTES);
        tma_bulk_g2s(buf_u32[1], imgs + 1*IMG_ELEMS, IMG_BYTES, mbar_u32 + 8);
    }

    // 2x2 output block coords: 16 x 24 blocks = 384 threads.
    const int by = tid / 24, bx = tid % 24;
    const int iy = 4*by,     ix = 4*bx;
    const int pos_tl = (2*by)*WO + 2*bx;
    const bool right_edge = (bx == 23);      // col 96 -> SAME pad
    const bool bot_edge   = (by == 15);      // row 64 -> SAME pad (r==4 only)

    for (int i = 0; i < 5; i++) {
        mbar_wait(mbar_u32 + 8*(i & 1), (i >> 1) & 1);   // image i ready

        const float* sb = buf[i & 1];

        // acc01[p] = (A0,B0) at pos p; acc23[p] = (A1,B1). p: tl,tr,bl,br
        u64 acc01[4], acc23[4];
        #pragma unroll
        for (int p = 0; p < 4; p++) { acc01[p] = 0ull; acc23[p] = 0ull; }

        #pragma unroll
        for (int c = 0; c < 3; c++) {
            #pragma unroll
            for (int r = 0; r < 5; r++) {
                float v[5];
                if (bot_edge && r == 4) {
                    #pragma unroll
                    for (int k = 0; k < 5; k++) v[k] = 0.f;
                } else {
                    const float* rp = sb + (c*HI + iy + r)*WI + ix;
                    float4 v4 = *(const float4*)rp;   // 16B-aligned (384B rows)
                    v[0] = v4.x; v[1] = v4.y; v[2] = v4.z; v[3] = v4.w;
                    v[4] = right_edge ? 0.f : rp[4];
                }
                u64 vv[5];
                #pragma unroll
                for (int k = 0; k < 5; k++) vv[k] = pack2(v[k], v[k]);

                if (r < 3) {                          // top pos pair, ky = r
                    #pragma unroll
                    for (int kx = 0; kx < 3; kx++) {
                        int t = c*9 + r*3 + kx;
                        acc01[0] = fma2(wp01[t], vv[kx],   acc01[0]);
                        acc01[1] = fma2(wp01[t], vv[kx+2], acc01[1]);
                        acc23[0] = fma2(wp23[t], vv[kx],   acc23[0]);
                        acc23[1] = fma2(wp23[t], vv[kx+2], acc23[1]);
                    }
                }
                if (r >= 2) {                         // bottom pos pair, ky = r-2
                    #pragma unroll
                    for (int kx = 0; kx < 3; kx++) {
                        int t = c*9 + (r-2)*3 + kx;
                        acc01[2] = fma2(wp01[t], vv[kx],   acc01[2]);
                        acc01[3] = fma2(wp01[t], vv[kx+2], acc01[3]);
                        acc23[2] = fma2(wp23[t], vv[kx],   acc23[2]);
                        acc23[3] = fma2(wp23[t], vv[kx+2], acc23[3]);
                    }
                }
            }
        }

        // Store packed planes as (A0,A1),(B0,B1); bias folded into A halves.
        const int poss[4] = { pos_tl, pos_tl + 1, pos_tl + WO, pos_tl + WO + 1 };
        #pragma unroll
        for (int p = 0; p < 4; p++) {
            float2 f01 = unpack2(acc01[p]);   // (a0, b0)
            float2 f23 = unpack2(acc23[p]);   // (a1, b1)
            union { __nv_bfloat162 h2[2]; uint2 u; } cv;
            cv.h2[0] = __floats2bfloat162_rn(f01.x + bias0, f23.x + bias1); // (A0,A1)
            cv.h2[1] = __floats2bfloat162_rn(f01.y,         f23.y);         // (B0,B1)
            *(uint2*)(pl + ((size_t)i*NPOS + poss[p])*4) = cv.u;
        }

        __syncthreads();                     // all threads done with buf[i&1]
        if (i < 3 && tid == 0) {             // refill with image i+2
            uint32_t m = mbar_u32 + 8*(i & 1);
            mbar_expect_tx(m, IMG_BYTES);
            tma_bulk_g2s(buf_u32[i & 1], imgs + (i+2)*IMG_ELEMS, IMG_BYTES, m);
        }
    }
    __syncthreads();                         // all planes visible

    // Combine (packed over channels): accp[q] accumulates (t + |t|) where
    // t = (A0_i+B0_j, A1_i+B1_j); relu(x) = (x+|x|)/2 exactly, 1/2 at store.
    u64 accp[25];
    #pragma unroll
    for (int q = 0; q < 25; q++) accp[q] = 0ull;
    const u64 ABSM = 0x7FFFFFFF7FFFFFFFull;

    #pragma unroll
    for (int pp = 0; pp < 4; pp++) {
        int pos = tid + pp*NTHR;
        u64 uA[5], uB[5];
        #pragma unroll
        for (int i = 0; i < 5; i++) {
            uint2 u = *(const uint2*)(pl + ((size_t)i*NPOS + pos)*4);
            float2 fa = __bfloat1622float2(*(__nv_bfloat162*)&u.x);  // (A0,A1)
            float2 fb = __bfloat1622float2(*(__nv_bfloat162*)&u.y);  // (B0,B1)
            uA[i] = pack2(fa.x, fa.y);
            uB[i] = pack2(fb.x, fb.y);
        }
        #pragma unroll
        for (int i = 0; i < 5; i++)
            #pragma unroll
            for (int j = 0; j < 5; j++) {
                u64 t = add2(uA[i], uB[j]);
                u64 a = t & ABSM;
                int q = i*5 + j;
                accp[q] = add2(accp[q], t);
                accp[q] = add2(accp[q], a);
            }
    }

    // Shuffle-first reduction.
    const int lane = tid & 31, wid = tid >> 5;
    #pragma unroll
    for (int q = 0; q < 25; q++) {
        float2 f = unpack2(accp[q]);
        float s0 = f.x, s1 = f.y;
        #pragma unroll
        for (int off = 16; off; off >>= 1) {
            s0 += __shfl_xor_sync(0xFFFFFFFFu, s0, off);
            s1 += __shfl_xor_sync(0xFFFFFFFFu, s1, off);
        }
        if (lane == 0) {
            red[q*2 + 0][wid] = s0;
            red[q*2 + 1][wid] = s1;
        }
    }
    __syncthreads();

    if (tid < 50) {
        float s = 0.f;
        #pragma unroll
        for (int k = 0; k < NWARP; k++) s += red[tid][k];
        int q  = tid >> 1;
        int ch = (tid & 1) ? c1 : c0;
        S[((size_t)z*NT + b*25 + q)*COUT + ch] = 0.5f * s;  // undo 2x from t+|t|
    }
}

// ---------------------------------------------------------------------------
// logits over BOTH states (3200 tuples): warp per tuple.
// ---------------------------------------------------------------------------
__global__ __launch_bounds__(256)
void logits_kernel(const float* __restrict__ S,    // [3200][128]
                   const float* __restrict__ w2,   // [4][32]
                   const float* __restrict__ b2,   // [4]
                   const float* __restrict__ temp,
                   float* __restrict__ out)        // [3200][4]
{
    const int lane = threadIdx.x & 31;
    const int t = blockIdx.x * 8 + (threadIdx.x >> 5);
    if (t >= 2*NT) return;

    float s[4];
    #pragma unroll
    for (int p = 0; p < 4; p++)
        s[p] = S[(size_t)t*COUT + p*32 + lane] * w2[p*32 + lane];
    #pragma unroll
    for (int off = 16; off; off >>= 1)
        #pragma unroll
        for (int p = 0; p < 4; p++)
            s[p] += __shfl_xor_sync(0xFFFFFFFFu, s[p], off);

    if (lane < 4) {
        float invT = 1.0f / (*temp);
        float logit = s[lane] * (1.0f / (float)NPOS) + b2[lane];
        out[t*4 + lane] = 1.0f / (1.0f + expf(-logit * invT));
    }
}

// adj[b][t] = (t / 25 == b)
__global__ void adj_kernel(float* __restrict__ out)
{
    int idx = blockIdx.x * blockDim.x + threadIdx.x;
    if (idx >= NB * NT) return;
    int b = idx / NT;
    int t = idx % NT;
    out[idx] = (t / (NOBJ*NOBJ) == b) ? 1.0f : 0.0f;
}

// ---------------------------------------------------------------------------
extern "C" void kernel_launch(void* const* d_in, const int* in_sizes, int n_in,
                              void* d_out, int out_size)
{
    const float* state      = (const float*)d_in[0];
    const float* state_next = (const float*)d_in[1];
    const float* conv_w     = (const float*)d_in[2];
    const float* conv_b     = (const float*)d_in[3];
    const float* w2         = (const float*)d_in[4];
    const float* b2         = (const float*)d_in[5];
    // d_in[6] = n_obj (constant NOBJ), d_in[7] = temp
    const float* temp       = (const float*)d_in[7];
    float* out = (float*)d_out;

    float* S;
    cudaGetSymbolAddress((void**)&S, g_S);

    cudaFuncSetAttribute(fused_kernel, cudaFuncAttributeMaxDynamicSharedMemorySize,
                         SMEM_BYTES);

    // Both states in ONE launch: grid (channel-pair, batch, state)
    fused_kernel<<<dim3(64, NB, 2), NTHR, SMEM_BYTES>>>(state, state_next,
                                                        conv_w, conv_b, S);

    // logits for both states (out = preds | preds_next, contiguous)
    logits_kernel<<<(2*NT + 7)/8, 256>>>(S, w2, b2, temp, out);

    // adjacency
    adj_kernel<<<(NB*NT + 255)/256, 256>>>(out + 2*NT*PP);
}

// round 11
// speedup vs baseline: 1.2460x; 1.2175x over previous
#include <cuda_runtime.h>
#include <cuda_bf16.h>
#include <cstdint>
#include <math.h>

// Problem constants
#define NB     64
#define NOBJ   5
#define CIN    3
#define HI     64
#define WI     96
#define HO     32
#define WO     48
#define NPOS   (HO*WO)          // 1536
#define COUT   128
#define PP     4
#define NT     (NB*NOBJ*NOBJ)   // 1600

#define NTHR   384              // 12 warps; 16x24 grid of 2x2 output blocks
#define NWARP  (NTHR/32)
#define GPER   8                // channel-pairs per persistent CTA

// Unpadded f32 image buffer: [3][64][96] = 73728 B (TMA bulk)
#define IMG_ELEMS (CIN*HI*WI)                  // 18432
#define IMG_BYTES (IMG_ELEMS*4)
// Planes (bf16): [5 img][1536 pos][4] packed (A0,A1),(B0,B1)
#define PL_BF16_ELEMS (5*NPOS*4)
// Weight stash: GPER pairs x 2 ch x 27 taps of u64
#define WSTASH_U64 (GPER*2*27)                 // 432 u64 = 3456 B
#define SMEM_BYTES (2*IMG_BYTES + PL_BF16_ELEMS*2 + WSTASH_U64*8)  // 181632 B

__device__ float g_S[(size_t)2 * NT * COUT];   // [2][1600][128]

typedef unsigned long long u64;

// ---- packed f32x2 helpers ---------------------------------------------------
__device__ __forceinline__ u64 pack2(float lo, float hi) {
    u64 r; asm("mov.b64 %0, {%1, %2};" : "=l"(r) : "f"(lo), "f"(hi)); return r;
}
__device__ __forceinline__ float2 unpack2(u64 v) {
    float2 f; asm("mov.b64 {%0, %1}, %2;" : "=f"(f.x), "=f"(f.y) : "l"(v)); return f;
}
__device__ __forceinline__ u64 fma2(u64 a, u64 b, u64 c) {
    u64 d; asm("fma.rn.f32x2 %0, %1, %2, %3;" : "=l"(d) : "l"(a), "l"(b), "l"(c)); return d;
}
__device__ __forceinline__ u64 add2(u64 a, u64 b) {
    u64 d; asm("add.rn.f32x2 %0, %1, %2;" : "=l"(d) : "l"(a), "l"(b)); return d;
}

// ---- TMA bulk + mbarrier helpers -------------------------------------------
__device__ __forceinline__ void mbar_init(uint32_t addr, uint32_t count) {
    asm volatile("mbarrier.init.shared.b64 [%0], %1;" :: "r"(addr), "r"(count) : "memory");
}
__device__ __forceinline__ void mbar_expect_tx(uint32_t addr, uint32_t bytes) {
    asm volatile("mbarrier.arrive.expect_tx.shared.b64 _, [%0], %1;"
                 :: "r"(addr), "r"(bytes) : "memory");
}
__device__ __forceinline__ void tma_bulk_g2s(uint32_t dst, const void* src,
                                             uint32_t bytes, uint32_t mbar) {
    asm volatile("cp.async.bulk.shared::cta.global.mbarrier::complete_tx::bytes "
                 "[%0], [%1], %2, [%3];"
                 :: "r"(dst), "l"(src), "r"(bytes), "r"(mbar) : "memory");
}
__device__ __forceinline__ void mbar_wait(uint32_t mbar, uint32_t parity) {
    uint32_t done;
    asm volatile(
        "{\n\t.reg .pred p;\n\t"
        "mbarrier.try_wait.parity.acquire.cta.shared::cta.b64 p, [%1], %2;\n\t"
        "selp.b32 %0, 1, 0, p;\n\t}"
        : "=r"(done) : "r"(mbar), "r"(parity) : "memory");
    if (!done) {
        asm volatile(
            "{\n\t.reg .pred P1;\n\t"
            "WAIT_LOOP_%=:\n\t"
            "mbarrier.try_wait.parity.acquire.cta.shared::cta.b64 P1, [%0], %1, 0x989680;\n\t"
            "@P1 bra.uni WAIT_DONE_%=;\n\t"
            "bra.uni WAIT_LOOP_%=;\n\t"
            "WAIT_DONE_%=:\n\t}"
            :: "r"(mbar), "r"(parity) : "memory");
    }
}

// ---------------------------------------------------------------------------
// Persistent fused conv + pairwise-combine.
// CTA = (gq, b, z) processes GPER=8 channel-pairs for batch b / state z.
// Ping-pong image order per k: the double buffers already contain the next
// iteration's first two images, so steady-state iterations start with zero
// TMA wait. conv(concat(img_i,img_j), W) = conv(img_i, W_a) + conv(img_j, W_b).
// ---------------------------------------------------------------------------
__global__ __launch_bounds__(NTHR, 1)
void fused_kernel(const float* __restrict__ input0,  // state  [320][3][64][96]
                  const float* __restrict__ input1,  // state_next
                  const float* __restrict__ conv_w,  // [128][6][3][3]
                  const float* __restrict__ conv_b,  // [128]
                  float* __restrict__ S)             // [2][1600][128]
{
    extern __shared__ __align__(16) float sm[];
    float* buf[2] = { sm, sm + IMG_ELEMS };
    __nv_bfloat16* pl = (__nv_bfloat16*)(sm + 2*IMG_ELEMS);
    u64* swp = (u64*)(pl + PL_BF16_ELEMS);     // [GPER][2][27] packed weights
    __shared__ float red[50][NWARP];
    __shared__ __align__(8) unsigned long long mbar_store[2];

    const int gq  = blockIdx.x;     // 0..7
    const int b   = blockIdx.y;     // 0..63
    const int z   = blockIdx.z;     // 0..1
    const int tid = threadIdx.x;

    uint32_t buf_u32[2];
    buf_u32[0] = (uint32_t)__cvta_generic_to_shared(buf[0]);
    buf_u32[1] = (uint32_t)__cvta_generic_to_shared(buf[1]);
    uint32_t mbar_u32 = (uint32_t)__cvta_generic_to_shared(mbar_store);

    const float* imgs = (z ? input1 : input0) + (size_t)b * NOBJ * IMG_ELEMS;

    // Prime: mbarriers + TMA for images 0,1 issued FIRST, weight prep overlaps.
    if (tid == 0) {
        mbar_init(mbar_u32 + 0, 1);
        mbar_init(mbar_u32 + 8, 1);
    }
    __syncthreads();
    if (tid == 0) {
        mbar_expect_tx(mbar_u32 + 0, IMG_BYTES);
        tma_bulk_g2s(buf_u32[0], imgs + 0*IMG_ELEMS, IMG_BYTES, mbar_u32 + 0);
        mbar_expect_tx(mbar_u32 + 8, IMG_BYTES);
        tma_bulk_g2s(buf_u32[1], imgs + 1*IMG_ELEMS, IMG_BYTES, mbar_u32 + 8);
    }

    // Pre-pack all GPER pairs' weights into smem (overlaps first TMA flight).
    for (int idx = tid; idx < GPER*2*27; idx += NTHR) {
        int k = idx / 54, rem = idx % 54;
        int which = rem / 27, t = rem % 27;
        int c = 2*(gq*GPER + k) + which;
        int ic = t / 9, kk = t % 9;
        swp[idx] = pack2(conv_w[(c*6 + ic)*9 + kk], conv_w[(c*6 + 3 + ic)*9 + kk]);
    }
    __syncthreads();

    // 2x2 output block coords: 16 x 24 blocks = 384 threads.
    const int by = tid / 24, bx = tid % 24;
    const int iy = 4*by,     ix = 4*bx;
    const int pos_tl = (2*by)*WO + 2*bx;
    const bool right_edge = (bx == 23);      // col 96 -> SAME pad
    const bool bot_edge   = (by == 15);      // row 64 -> SAME pad (r==4 only)

    int wpar[2] = {0, 0};                    // next wait parity per buffer

    for (int k = 0; k < GPER; k++) {
        const int g  = gq*GPER + k;
        const int c0 = 2*g, c1 = 2*g + 1;
        const int dir = k & 1;               // ping-pong image order

        // Per-pair weights: broadcast LDS from the stash.
        u64 wp01[27], wp23[27];
        #pragma unroll
        for (int t = 0; t < 27; t++) {
            wp01[t] = swp[k*54 +      t];
            wp23[t] = swp[k*54 + 27 + t];
        }
        const float bias0 = conv_b[c0];
        const float bias1 = conv_b[c1];

        for (int p = 0; p < 5; p++) {
            const int img = dir ? (4 - p) : p;
            const int s   = p & 1;
            const bool waited = (k == 0) || (p >= 2);   // TMA issued for this slot
            if (waited) {
                mbar_wait(mbar_u32 + 8*s, wpar[s]);
                wpar[s] ^= 1;
            }

            const float* sb = buf[s];

            // acc01[q] = (A0,B0) at pos q; acc23[q] = (A1,B1). q: tl,tr,bl,br
            u64 acc01[4], acc23[4];
            #pragma unroll
            for (int q = 0; q < 4; q++) { acc01[q] = 0ull; acc23[q] = 0ull; }

            #pragma unroll
            for (int c = 0; c < 3; c++) {
                #pragma unroll
                for (int r = 0; r < 5; r++) {
                    float v[5];
                    if (bot_edge && r == 4) {
                        #pragma unroll
                        for (int kk = 0; kk < 5; kk++) v[kk] = 0.f;
                    } else {
                        const float* rp = sb + (c*HI + iy + r)*WI + ix;
                        float4 v4 = *(const float4*)rp;   // 16B-aligned
                        v[0] = v4.x; v[1] = v4.y; v[2] = v4.z; v[3] = v4.w;
                        v[4] = right_edge ? 0.f : rp[4];
                    }
                    u64 vv[5];
                    #pragma unroll
                    for (int kk = 0; kk < 5; kk++) vv[kk] = pack2(v[kk], v[kk]);

                    if (r < 3) {                          // top pos pair, ky = r
                        #pragma unroll
                        for (int kx = 0; kx < 3; kx++) {
                            int t = c*9 + r*3 + kx;
                            acc01[0] = fma2(wp01[t], vv[kx],   acc01[0]);
                            acc01[1] = fma2(wp01[t], vv[kx+2], acc01[1]);
                            acc23[0] = fma2(wp23[t], vv[kx],   acc23[0]);
                            acc23[1] = fma2(wp23[t], vv[kx+2], acc23[1]);
                        }
                    }
                    if (r >= 2) {                         // bottom pos pair, ky = r-2
                        #pragma unroll
                        for (int kx = 0; kx < 3; kx++) {
                            int t = c*9 + (r-2)*3 + kx;
                            acc01[2] = fma2(wp01[t], vv[kx],   acc01[2]);
                            acc01[3] = fma2(wp01[t], vv[kx+2], acc01[3]);
                            acc23[2] = fma2(wp23[t], vv[kx],   acc23[2]);
                            acc23[3] = fma2(wp23[t], vv[kx+2], acc23[3]);
                        }
                    }
                }
            }

            // Store planes as (A0,A1),(B0,B1); bias folded into A halves.
            const int poss[4] = { pos_tl, pos_tl + 1, pos_tl + WO, pos_tl + WO + 1 };
            #pragma unroll
            for (int q = 0; q < 4; q++) {
                float2 f01 = unpack2(acc01[q]);   // (a0, b0)
                float2 f23 = unpack2(acc23[q]);   // (a1, b1)
                union { __nv_bfloat162 h2[2]; uint2 u; } cv;
                cv.h2[0] = __floats2bfloat162_rn(f01.x + bias0, f23.x + bias1);
                cv.h2[1] = __floats2bfloat162_rn(f01.y,         f23.y);
                *(uint2*)(pl + ((size_t)img*NPOS + poss[q])*4) = cv.u;
            }

            __syncthreads();                     // all threads done with buf[s]
            if (p + 2 <= 4 && tid == 0) {        // refill slot s with image for p+2
                const int nimg = dir ? (4 - (p+2)) : (p+2);
                uint32_t m = mbar_u32 + 8*s;
                mbar_expect_tx(m, IMG_BYTES);
                tma_bulk_g2s(buf_u32[s], imgs + (size_t)nimg*IMG_ELEMS, IMG_BYTES, m);
            }
        }
        // NOTE: after p-loop, buffers hold the next k's first two images.

        // Combine (packed over channels): accp[q] += (t + |t|),
        // t = (A0_i+B0_j, A1_i+B1_j); relu(x) = (x+|x|)/2 exactly, 1/2 at store.
        u64 accp[25];
        #pragma unroll
        for (int q = 0; q < 25; q++) accp[q] = 0ull;
        const u64 ABSM = 0x7FFFFFFF7FFFFFFFull;

        #pragma unroll
        for (int ppos = 0; ppos < 4; ppos++) {
            int pos = tid + ppos*NTHR;
            u64 uA[5], uB[5];
            #pragma unroll
            for (int i = 0; i < 5; i++) {
                uint2 u = *(const uint2*)(pl + ((size_t)i*NPOS + pos)*4);
                float2 fa = __bfloat1622float2(*(__nv_bfloat162*)&u.x);  // (A0,A1)
                float2 fb = __bfloat1622float2(*(__nv_bfloat162*)&u.y);  // (B0,B1)
                uA[i] = pack2(fa.x, fa.y);
                uB[i] = pack2(fb.x, fb.y);
            }
            #pragma unroll
            for (int i = 0; i < 5; i++)
                #pragma unroll
                for (int j = 0; j < 5; j++) {
                    u64 t = add2(uA[i], uB[j]);
                    u64 a = t & ABSM;
                    int q = i*5 + j;
                    accp[q] = add2(accp[q], t);
                    accp[q] = add2(accp[q], a);
                }
        }

        // Shuffle-first reduction.
        const int lane = tid & 31, wid = tid >> 5;
        #pragma unroll
        for (int q = 0; q < 25; q++) {
            float2 f = unpack2(accp[q]);
            float s0 = f.x, s1 = f.y;
            #pragma unroll
            for (int off = 16; off; off >>= 1) {
                s0 += __shfl_xor_sync(0xFFFFFFFFu, s0, off);
                s1 += __shfl_xor_sync(0xFFFFFFFFu, s1, off);
            }
            if (lane == 0) {
                red[q*2 + 0][wid] = s0;
                red[q*2 + 1][wid] = s1;
            }
        }
        __syncthreads();

        if (tid < 50) {
            float ssum = 0.f;
            #pragma unroll
            for (int kk = 0; kk < NWARP; kk++) ssum += red[tid][kk];
            int q  = tid >> 1;
            int ch = (tid & 1) ? c1 : c0;
            S[((size_t)z*NT + b*25 + q)*COUT + ch] = 0.5f * ssum;
        }
        __syncthreads();       // red[] reuse + planes overwrite next k
    }
}

// ---------------------------------------------------------------------------
// logits over BOTH states (3200 tuples): warp per tuple.
// ---------------------------------------------------------------------------
__global__ __launch_bounds__(256)
void logits_kernel(const float* __restrict__ S,    // [3200][128]
                   const float* __restrict__ w2,   // [4][32]
                   const float* __restrict__ b2,   // [4]
                   const float* __restrict__ temp,
                   float* __restrict__ out)        // [3200][4]
{
    const int lane = threadIdx.x & 31;
    const int t = blockIdx.x * 8 + (threadIdx.x >> 5);
    if (t >= 2*NT) return;

    float s[4];
    #pragma unroll
    for (int p = 0; p < 4; p++)
        s[p] = S[(size_t)t*COUT + p*32 + lane] * w2[p*32 + lane];
    #pragma unroll
    for (int off = 16; off; off >>= 1)
        #pragma unroll
        for (int p = 0; p < 4; p++)
            s[p] += __shfl_xor_sync(0xFFFFFFFFu, s[p], off);

    if (lane < 4) {
        float invT = 1.0f / (*temp);
        float logit = s[lane] * (1.0f / (float)NPOS) + b2[lane];
        out[t*4 + lane] = 1.0f / (1.0f + expf(-logit * invT));
    }
}

// adj[b][t] = (t / 25 == b)
__global__ void adj_kernel(float* __restrict__ out)
{
    int idx = blockIdx.x * blockDim.x + threadIdx.x;
    if (idx >= NB * NT) return;
    int b = idx / NT;
    int t = idx % NT;
    out[idx] = (t / (NOBJ*NOBJ) == b) ? 1.0f : 0.0f;
}

// ---------------------------------------------------------------------------
extern "C" void kernel_launch(void* const* d_in, const int* in_sizes, int n_in,
                              void* d_out, int out_size)
{
    const float* state      = (const float*)d_in[0];
    const float* state_next = (const float*)d_in[1];
    const float* conv_w     = (const float*)d_in[2];
    const float* conv_b     = (const float*)d_in[3];
    const float* w2         = (const float*)d_in[4];
    const float* b2         = (const float*)d_in[5];
    // d_in[6] = n_obj (constant NOBJ), d_in[7] = temp
    const float* temp       = (const float*)d_in[7];
    float* out = (float*)d_out;

    float* S;
    cudaGetSymbolAddress((void**)&S, g_S);

    cudaFuncSetAttribute(fused_kernel, cudaFuncAttributeMaxDynamicSharedMemorySize,
                         SMEM_BYTES);

    // Persistent CTAs: grid (gq, batch, state) = 1024 CTAs, 8 channel-pairs each
    fused_kernel<<<dim3(GPER, NB, 2), NTHR, SMEM_BYTES>>>(state, state_next,
                                                          conv_w, conv_b, S);

    // logits for both states (out = preds | preds_next, contiguous)
    logits_kernel<<<(2*NT + 7)/8, 256>>>(S, w2, b2, temp, out);

    // adjacency
    adj_kernel<<<(NB*NT + 255)/256, 256>>>(out + 2*NT*PP);
}

// round 15
// speedup vs baseline: 1.3000x; 1.0433x over previous
#include <cuda_runtime.h>
#include <cuda_bf16.h>
#include <cstdint>
#include <math.h>

// Problem constants
#define NB     64
#define NOBJ   5
#define NIMG   (NB*NOBJ)        // 320 images per state
#define CIN    3
#define HI     64
#define WI     96
#define HO     32
#define WO     48
#define NPOS   (HO*WO)          // 1536
#define COUT   128
#define PP     4
#define NT     (NB*NOBJ*NOBJ)   // 1600

#define NTHR   384              // 12 warps; 16x24 grid of 2x2 output blocks
#define NWARP  (NTHR/32)
#define GPER   8                // channel-pairs per persistent CTA

#define IMG_ELEMS (CIN*HI*WI)               // 18432
#define IMG_BF16_BYTES (IMG_ELEMS*2)        // 36864
// smem: 5 resident bf16 images + weight stash [GPER][3c][2 half][9] u64
#define WSTASH_U64 (GPER*3*2*9)             // 432
#define SMEM_BYTES (5*IMG_BF16_BYTES + WSTASH_U64*8)   // 184320+3456 = 187776

// Static scratch
__device__ __nv_bfloat16 g_imgs[(size_t)2 * NIMG * IMG_ELEMS];  // 23.6 MB
__device__ float g_S[(size_t)2 * NT * COUT];                    // 3.2 MB

typedef unsigned long long u64;

// ---- packed f32x2 helpers ---------------------------------------------------
__device__ __forceinline__ u64 pack2(float lo, float hi) {
    u64 r; asm("mov.b64 %0, {%1, %2};" : "=l"(r) : "f"(lo), "f"(hi)); return r;
}
__device__ __forceinline__ float2 unpack2(u64 v) {
    float2 f; asm("mov.b64 {%0, %1}, %2;" : "=f"(f.x), "=f"(f.y) : "l"(v)); return f;
}
__device__ __forceinline__ u64 fma2(u64 a, u64 b, u64 c) {
    u64 d; asm("fma.rn.f32x2 %0, %1, %2, %3;" : "=l"(d) : "l"(a), "l"(b), "l"(c)); return d;
}
__device__ __forceinline__ u64 add2(u64 a, u64 b) {
    u64 d; asm("add.rn.f32x2 %0, %1, %2;" : "=l"(d) : "l"(a), "l"(b)); return d;
}
// bf16 (lo/hi of a u32) -> duplicated f32x2 (v,v); exact (<<16)
__device__ __forceinline__ u64 dup_lo(uint32_t u) {
    float f = __uint_as_float(u << 16); return pack2(f, f);
}
__device__ __forceinline__ u64 dup_hi(uint32_t u) {
    float f = __uint_as_float(u & 0xFFFF0000u); return pack2(f, f);
}

// ---- TMA bulk + mbarrier helpers -------------------------------------------
__device__ __forceinline__ void mbar_init(uint32_t addr, uint32_t count) {
    asm volatile("mbarrier.init.shared.b64 [%0], %1;" :: "r"(addr), "r"(count) : "memory");
}
__device__ __forceinline__ void mbar_expect_tx(uint32_t addr, uint32_t bytes) {
    asm volatile("mbarrier.arrive.expect_tx.shared.b64 _, [%0], %1;"
                 :: "r"(addr), "r"(bytes) : "memory");
}
__device__ __forceinline__ void tma_bulk_g2s(uint32_t dst, const void* src,
                                             uint32_t bytes, uint32_t mbar) {
    asm volatile("cp.async.bulk.shared::cta.global.mbarrier::complete_tx::bytes "
                 "[%0], [%1], %2, [%3];"
                 :: "r"(dst), "l"(src), "r"(bytes), "r"(mbar) : "memory");
}
__device__ __forceinline__ void mbar_wait(uint32_t mbar, uint32_t parity) {
    uint32_t done;
    asm volatile(
        "{\n\t.reg .pred p;\n\t"
        "mbarrier.try_wait.parity.acquire.cta.shared::cta.b64 p, [%1], %2;\n\t"
        "selp.b32 %0, 1, 0, p;\n\t}"
        : "=r"(done) : "r"(mbar), "r"(parity) : "memory");
    if (!done) {
        asm volatile(
            "{\n\t.reg .pred P1;\n\t"
            "WAIT_LOOP_%=:\n\t"
            "mbarrier.try_wait.parity.acquire.cta.shared::cta.b64 P1, [%0], %1, 0x989680;\n\t"
            "@P1 bra.uni WAIT_DONE_%=;\n\t"
            "bra.uni WAIT_LOOP_%=;\n\t"
            "WAIT_DONE_%=:\n\t}"
            :: "r"(mbar), "r"(parity) : "memory");
    }
}

// ---------------------------------------------------------------------------
// fp32 -> bf16 image conversion (both states)
// ---------------------------------------------------------------------------
#define N4PS (NIMG*IMG_ELEMS/4)
__global__ __launch_bounds__(256)
void cvt_kernel(const float* __restrict__ a, const float* __restrict__ bsrc,
                __nv_bfloat16* __restrict__ out)
{
    int i = blockIdx.x * blockDim.x + threadIdx.x;
    if (i >= 2*N4PS) return;
    const float* src = (i < N4PS) ? a : bsrc;
    int j = (i < N4PS) ? i : i - N4PS;
    float4 v = ((const float4*)src)[j];
    union { __nv_bfloat162 h2[2]; uint2 u; } cv;
    cv.h2[0] = __floats2bfloat162_rn(v.x, v.y);
    cv.h2[1] = __floats2bfloat162_rn(v.z, v.w);
    ((uint2*)out)[i] = cv.u;
}

// ---------------------------------------------------------------------------
// Persistent fused conv + pairwise-combine, barrier-free mainloop.
// CTA = (gq, b, z): 5 bf16 images resident in smem (TMA'd once),
// GPER=8 channel-pairs; conv accumulators (f32x2 channel-packed) live in
// registers straight into the combine — planes never touch smem.
// conv(concat(img_i,img_j), W) = conv(img_i, W_a) + conv(img_j, W_b).
// ---------------------------------------------------------------------------
__global__ __launch_bounds__(NTHR, 1)
void fused_kernel(const __nv_bfloat16* __restrict__ gimgs,
                  const float* __restrict__ conv_w,  // [128][6][3][3]
                  const float* __restrict__ conv_b,  // [128]
                  float* __restrict__ S)             // [2][1600][128]
{
    extern __shared__ __align__(16) char smc[];
    const __nv_bfloat16* simg = (const __nv_bfloat16*)smc;    // [5][18432]
    u64* swp = (u64*)(smc + 5*IMG_BF16_BYTES);                // [GPER][3][2][9]
    __shared__ float red[50][NWARP];
    __shared__ __align__(8) unsigned long long mbar_store[1];

    const int gq  = blockIdx.x;     // 0..7
    const int b   = blockIdx.y;     // 0..63
    const int z   = blockIdx.z;     // 0..1
    const int tid = threadIdx.x;

    uint32_t smem_u32 = (uint32_t)__cvta_generic_to_shared(smc);
    uint32_t mbar_u32 = (uint32_t)__cvta_generic_to_shared(mbar_store);

    const __nv_bfloat16* gsrc = gimgs + ((size_t)(z*NB + b) * NOBJ) * IMG_ELEMS;

    // Prologue: TMA all 5 images once; stash weights while TMA flies.
    if (tid == 0) mbar_init(mbar_u32, 1);
    __syncthreads();
    if (tid == 0) {
        mbar_expect_tx(mbar_u32, 5*IMG_BF16_BYTES);
        #pragma unroll
        for (int i = 0; i < 5; i++)
            tma_bulk_g2s(smem_u32 + i*IMG_BF16_BYTES, gsrc + (size_t)i*IMG_ELEMS,
                         IMG_BF16_BYTES, mbar_u32);
    }
    // Weight stash, channel-packed: swp[((k*3+c)*2+h)*9+t] =
    //   ( half_h weight of ch 2(gq*8+k)   [input-ch c, tap t],
    //     half_h weight of ch 2(gq*8+k)+1 )   h=0: W_a, h=1: W_b
    for (int idx = tid; idx < WSTASH_U64; idx += NTHR) {
        int k = idx / 54, rem = idx % 54;
        int c = rem / 18, h = (rem % 18) / 9, t9 = rem % 9;
        int g = gq*GPER + k;
        int off = h ? 3 : 0;
        float w0 = conv_w[((2*g  )*6 + off + c)*9 + t9];
        float w1 = conv_w[((2*g+1)*6 + off + c)*9 + t9];
        swp[idx] = pack2(w0, w1);
    }
    mbar_wait(mbar_u32, 0);
    __syncthreads();              // images + stash visible

    // 2x2 output block coords: 16 x 24 blocks = 384 threads.
    const int by = tid / 24, bx = tid % 24;
    const int iy = 4*by,     ix = 4*bx;
    const int pos_base = iy*WO + 2*bx;           // == (2*by)*WO + 2*bx? (2by)*48
    const bool right_edge = (bx == 23);
    const bool bot_edge   = (by == 15);
    const u64 ABSM = 0x7FFFFFFF7FFFFFFFull;
    (void)pos_base;

    #pragma unroll 1
    for (int k = 0; k < GPER; k++) {
        const int g  = gq*GPER + k;
        const int c0 = 2*g, c1 = 2*g + 1;

        // accA[img][pos] = (A(c0), A(c1)); accB likewise. pos: tl,tr,bl,br
        u64 accA[5][4], accB[5][4];
        #pragma unroll
        for (int i = 0; i < 5; i++)
            #pragma unroll
            for (int p = 0; p < 4; p++) { accA[i][p] = 0ull; accB[i][p] = 0ull; }

        #pragma unroll
        for (int c = 0; c < 3; c++) {
            // per input-channel weights (broadcast LDS)
            u64 wA[9], wB[9];
            #pragma unroll
            for (int t = 0; t < 9; t++) {
                wA[t] = swp[((k*3 + c)*2 + 0)*9 + t];
                wB[t] = swp[((k*3 + c)*2 + 1)*9 + t];
            }
            #pragma unroll
            for (int i = 0; i < 5; i++) {
                const __nv_bfloat16* base = simg + (size_t)i*IMG_ELEMS
                                          + (c*HI + iy)*WI + ix;
                #pragma unroll
                for (int r = 0; r < 5; r++) {
                    u64 vv[5];
                    if (bot_edge && r == 4) {
                        #pragma unroll
                        for (int q = 0; q < 5; q++) vv[q] = 0ull;
                    } else {
                        const char* rp = (const char*)(base + r*WI);
                        uint2 u2 = *(const uint2*)rp;          // v0..v3 (8B-aligned)
                        uint32_t u4 = *(const uint32_t*)(rp + 8); // v4,(v5)
                        vv[0] = dup_lo(u2.x);
                        vv[1] = dup_hi(u2.x);
                        vv[2] = dup_lo(u2.y);
                        vv[3] = dup_hi(u2.y);
                        vv[4] = right_edge ? 0ull : dup_lo(u4);
                    }
                    if (r < 3) {                   // top out-row, ky = r
                        #pragma unroll
                        for (int kx = 0; kx < 3; kx++) {
                            int t = r*3 + kx;
                            accA[i][0] = fma2(wA[t], vv[kx],   accA[i][0]);
                            accA[i][1] = fma2(wA[t], vv[kx+2], accA[i][1]);
                            accB[i][0] = fma2(wB[t], vv[kx],   accB[i][0]);
                            accB[i][1] = fma2(wB[t], vv[kx+2], accB[i][1]);
                        }
                    }
                    if (r >= 2) {                  // bottom out-row, ky = r-2
                        #pragma unroll
                        for (int kx = 0; kx < 3; kx++) {
                            int t = (r-2)*3 + kx;
                            accA[i][2] = fma2(wA[t], vv[kx],   accA[i][2]);
                            accA[i][3] = fma2(wA[t], vv[kx+2], accA[i][3]);
                            accB[i][2] = fma2(wB[t], vv[kx],   accB[i][2]);
                            accB[i][3] = fma2(wB[t], vv[kx+2], accB[i][3]);
                        }
                    }
                }
            }
        }

        // Fold bias into A accumulators.
        const u64 bias2 = pack2(__ldg(conv_b + c0), __ldg(conv_b + c1));
        #pragma unroll
        for (int i = 0; i < 5; i++)
            #pragma unroll
            for (int p = 0; p < 4; p++)
                accA[i][p] = add2(accA[i][p], bias2);

        // Combine directly from registers: accp[q] += (t + |t|),
        // t = A_i + B_j; relu(x) = (x+|x|)/2 exactly, 1/2 applied at store.
        u64 accp[25];
        #pragma unroll
        for (int q = 0; q < 25; q++) accp[q] = 0ull;
        #pragma unroll
        for (int p = 0; p < 4; p++)
            #pragma unroll
            for (int i = 0; i < 5; i++)
                #pragma unroll
                for (int j = 0; j < 5; j++) {
                    u64 t = add2(accA[i][p], accB[j][p]);
                    int q = i*5 + j;
                    accp[q] = add2(accp[q], t);
                    accp[q] = add2(accp[q], t & ABSM);
                }

        // Shuffle-first reduction (lanes: lo=c0, hi=c1).
        const int lane = tid & 31, wid = tid >> 5;
        #pragma unroll
        for (int q = 0; q < 25; q++) {
            float2 f = unpack2(accp[q]);
            float s0 = f.x, s1 = f.y;
            #pragma unroll
            for (int off = 16; off; off >>= 1) {
                s0 += __shfl_xor_sync(0xFFFFFFFFu, s0, off);
                s1 += __shfl_xor_sync(0xFFFFFFFFu, s1, off);
            }
            if (lane == 0) {
                red[q*2 + 0][wid] = s0;
                red[q*2 + 1][wid] = s1;
            }
        }
        __syncthreads();

        if (tid < 50) {
            float ssum = 0.f;
            #pragma unroll
            for (int kk = 0; kk < NWARP; kk++) ssum += red[tid][kk];
            int q  = tid >> 1;
            int ch = (tid & 1) ? c1 : c0;
            S[((size_t)z*NT + b*25 + q)*COUT + ch] = 0.5f * ssum;
        }
        __syncthreads();        // red[] reuse next k
    }
}

// ---------------------------------------------------------------------------
// logits over BOTH states (3200 tuples): warp per tuple.
// ---------------------------------------------------------------------------
__global__ __launch_bounds__(256)
void logits_kernel(const float* __restrict__ S,    // [3200][128]
                   const float* __restrict__ w2,   // [4][32]
                   const float* __restrict__ b2,   // [4]
                   const float* __restrict__ temp,
                   float* __restrict__ out)        // [3200][4]
{
    const int lane = threadIdx.x & 31;
    const int t = blockIdx.x * 8 + (threadIdx.x >> 5);
    if (t >= 2*NT) return;

    float s[4];
    #pragma unroll
    for (int p = 0; p < 4; p++)
        s[p] = S[(size_t)t*COUT + p*32 + lane] * w2[p*32 + lane];
    #pragma unroll
    for (int off = 16; off; off >>= 1)
        #pragma unroll
        for (int p = 0; p < 4; p++)
            s[p] += __shfl_xor_sync(0xFFFFFFFFu, s[p], off);

    if (lane < 4) {
        float invT = 1.0f / (*temp);
        float logit = s[lane] * (1.0f / (float)NPOS) + b2[lane];
        out[t*4 + lane] = 1.0f / (1.0f + expf(-logit * invT));
    }
}

// adj[b][t] = (t / 25 == b)
__global__ void adj_kernel(float* __restrict__ out)
{
    int idx = blockIdx.x * blockDim.x + threadIdx.x;
    if (idx >= NB * NT) return;
    int b = idx / NT;
    int t = idx % NT;
    out[idx] = (t / (NOBJ*NOBJ) == b) ? 1.0f : 0.0f;
}

// ---------------------------------------------------------------------------
extern "C" void kernel_launch(void* const* d_in, const int* in_sizes, int n_in,
                              void* d_out, int out_size)
{
    const float* state      = (const float*)d_in[0];
    const float* state_next = (const float*)d_in[1];
    const float* conv_w     = (const float*)d_in[2];
    const float* conv_b     = (const float*)d_in[3];
    const float* w2         = (const float*)d_in[4];
    const float* b2         = (const float*)d_in[5];
    // d_in[6] = n_obj (constant NOBJ), d_in[7] = temp
    const float* temp       = (const float*)d_in[7];
    float* out = (float*)d_out;

    __nv_bfloat16* imgs; cudaGetSymbolAddress((void**)&imgs, g_imgs);
    float* S;            cudaGetSymbolAddress((void**)&S, g_S);

    cudaFuncSetAttribute(fused_kernel, cudaFuncAttributeMaxDynamicSharedMemorySize,
                         SMEM_BYTES);

    // 1) convert both states' images to bf16
    cvt_kernel<<<(2*N4PS + 255)/256, 256>>>(state, state_next, imgs);

    // 2) persistent fused conv+combine: grid (gq, batch, state) = 1024 CTAs
    fused_kernel<<<dim3(GPER, NB, 2), NTHR, SMEM_BYTES>>>(imgs, conv_w, conv_b, S);

    // 3) logits for both states (out = preds | preds_next, contiguous)
    logits_kernel<<<(2*NT + 7)/8, 256>>>(S, w2, b2, temp, out);

    // 4) adjacency
    adj_kernel<<<(NB*NT + 255)/256, 256>>>(out + 2*NT*PP);
}

// round 17
// speedup vs baseline: 1.4185x; 1.0912x over previous
#include <cuda_runtime.h>
#include <cuda_bf16.h>
#include <cstdint>
#include <math.h>

// Problem constants
#define NB     64
#define NOBJ   5
#define NIMG   (NB*NOBJ)        // 320 images per state
#define CIN    3
#define HI     64
#define WI     96
#define HO     32
#define WO     48
#define NPOS   (HO*WO)          // 1536
#define COUT   128
#define PP     4
#define NT     (NB*NOBJ*NOBJ)   // 1600

#define NTHR   384              // 12 warps; 16x24 grid of 2x2 output blocks
#define NWARP  (NTHR/32)
#define GPER   8                // channel-pairs per persistent CTA

#define IMG_ELEMS (CIN*HI*WI)               // 18432
#define IMG_BF16_BYTES (IMG_ELEMS*2)        // 36864
// smem: 5 resident bf16 images + weight stash + reduction scratch
#define WSTASH_U64 (GPER*3*2*9)             // 432
#define RSCR_U64   (9*NTHR)                 // 3456 u64 = 27648 B
#define SMEM_BYTES (5*IMG_BF16_BYTES + WSTASH_U64*8 + RSCR_U64*8)  // 215424

// Static scratch
__device__ __nv_bfloat16 g_imgs[(size_t)2 * NIMG * IMG_ELEMS];  // 23.6 MB
__device__ float g_S[(size_t)2 * NT * COUT];                    // 3.2 MB

typedef unsigned long long u64;

// ---- packed f32x2 helpers ---------------------------------------------------
__device__ __forceinline__ u64 pack2(float lo, float hi) {
    u64 r; asm("mov.b64 %0, {%1, %2};" : "=l"(r) : "f"(lo), "f"(hi)); return r;
}
__device__ __forceinline__ float2 unpack2(u64 v) {
    float2 f; asm("mov.b64 {%0, %1}, %2;" : "=f"(f.x), "=f"(f.y) : "l"(v)); return f;
}
__device__ __forceinline__ u64 fma2(u64 a, u64 b, u64 c) {
    u64 d; asm("fma.rn.f32x2 %0, %1, %2, %3;" : "=l"(d) : "l"(a), "l"(b), "l"(c)); return d;
}
__device__ __forceinline__ u64 add2(u64 a, u64 b) {
    u64 d; asm("add.rn.f32x2 %0, %1, %2;" : "=l"(d) : "l"(a), "l"(b)); return d;
}
// bf16 (lo/hi of a u32) -> duplicated f32x2 (v,v); exact (<<16)
__device__ __forceinline__ u64 dup_lo(uint32_t u) {
    float f = __uint_as_float(u << 16); return pack2(f, f);
}
__device__ __forceinline__ u64 dup_hi(uint32_t u) {
    float f = __uint_as_float(u & 0xFFFF0000u); return pack2(f, f);
}

// ---- TMA bulk + mbarrier helpers -------------------------------------------
__device__ __forceinline__ void mbar_init(uint32_t addr, uint32_t count) {
    asm volatile("mbarrier.init.shared.b64 [%0], %1;" :: "r"(addr), "r"(count) : "memory");
}
__device__ __forceinline__ void mbar_expect_tx(uint32_t addr, uint32_t bytes) {
    asm volatile("mbarrier.arrive.expect_tx.shared.b64 _, [%0], %1;"
                 :: "r"(addr), "r"(bytes) : "memory");
}
__device__ __forceinline__ void tma_bulk_g2s(uint32_t dst, const void* src,
                                             uint32_t bytes, uint32_t mbar) {
    asm volatile("cp.async.bulk.shared::cta.global.mbarrier::complete_tx::bytes "
                 "[%0], [%1], %2, [%3];"
                 :: "r"(dst), "l"(src), "r"(bytes), "r"(mbar) : "memory");
}
__device__ __forceinline__ void mbar_wait(uint32_t mbar, uint32_t parity) {
    uint32_t done;
    asm volatile(
        "{\n\t.reg .pred p;\n\t"
        "mbarrier.try_wait.parity.acquire.cta.shared::cta.b64 p, [%1], %2;\n\t"
        "selp.b32 %0, 1, 0, p;\n\t}"
        : "=r"(done) : "r"(mbar), "r"(parity) : "memory");
    if (!done) {
        asm volatile(
            "{\n\t.reg .pred P1;\n\t"
            "WAIT_LOOP_%=:\n\t"
            "mbarrier.try_wait.parity.acquire.cta.shared::cta.b64 P1, [%0], %1, 0x989680;\n\t"
            "@P1 bra.uni WAIT_DONE_%=;\n\t"
            "bra.uni WAIT_LOOP_%=;\n\t"
            "WAIT_DONE_%=:\n\t}"
            :: "r"(mbar), "r"(parity) : "memory");
    }
}

// ---------------------------------------------------------------------------
// fp32 -> bf16 image conversion (both states)
// ---------------------------------------------------------------------------
#define N4PS (NIMG*IMG_ELEMS/4)
__global__ __launch_bounds__(256)
void cvt_kernel(const float* __restrict__ a, const float* __restrict__ bsrc,
                __nv_bfloat16* __restrict__ out)
{
    int i = blockIdx.x * blockDim.x + threadIdx.x;
    if (i >= 2*N4PS) return;
    const float* src = (i < N4PS) ? a : bsrc;
    int j = (i < N4PS) ? i : i - N4PS;
    float4 v = ((const float4*)src)[j];
    union { __nv_bfloat162 h2[2]; uint2 u; } cv;
    cv.h2[0] = __floats2bfloat162_rn(v.x, v.y);
    cv.h2[1] = __floats2bfloat162_rn(v.z, v.w);
    ((uint2*)out)[i] = cv.u;
}

// ---------------------------------------------------------------------------
// Persistent fused conv + pairwise-combine, register-resident planes,
// smem-transpose reduction.
// CTA = (gq, b, z): 5 bf16 images resident in smem (TMA'd once),
// GPER=8 channel-pairs; conv accumulators (f32x2 channel-packed) live in
// registers straight into the combine.
// conv(concat(img_i,img_j), W) = conv(img_i, W_a) + conv(img_j, W_b).
// ---------------------------------------------------------------------------
__global__ __launch_bounds__(NTHR, 1)
void fused_kernel(const __nv_bfloat16* __restrict__ gimgs,
                  const float* __restrict__ conv_w,  // [128][6][3][3]
                  const float* __restrict__ conv_b,  // [128]
                  float* __restrict__ S)             // [2][1600][128]
{
    extern __shared__ __align__(16) char smc[];
    const __nv_bfloat16* simg = (const __nv_bfloat16*)smc;    // [5][18432]
    u64* swp  = (u64*)(smc + 5*IMG_BF16_BYTES);               // [GPER][3][2][9]
    u64* rscr = swp + WSTASH_U64;                             // [9][NTHR]
    __shared__ __align__(8) unsigned long long mbar_store[1];

    const int gq  = blockIdx.x;     // 0..7
    const int b   = blockIdx.y;     // 0..63
    const int z   = blockIdx.z;     // 0..1
    const int tid = threadIdx.x;

    uint32_t smem_u32 = (uint32_t)__cvta_generic_to_shared(smc);
    uint32_t mbar_u32 = (uint32_t)__cvta_generic_to_shared(mbar_store);

    const __nv_bfloat16* gsrc = gimgs + ((size_t)(z*NB + b) * NOBJ) * IMG_ELEMS;

    // Prologue: TMA all 5 images once; stash weights while TMA flies.
    if (tid == 0) mbar_init(mbar_u32, 1);
    __syncthreads();
    if (tid == 0) {
        mbar_expect_tx(mbar_u32, 5*IMG_BF16_BYTES);
        #pragma unroll
        for (int i = 0; i < 5; i++)
            tma_bulk_g2s(smem_u32 + i*IMG_BF16_BYTES, gsrc + (size_t)i*IMG_ELEMS,
                         IMG_BF16_BYTES, mbar_u32);
    }
    // Weight stash, channel-packed: swp[((k*3+c)*2+h)*9+t] =
    //   (half_h weight of ch 2(gq*8+k), half_h weight of ch 2(gq*8+k)+1)
    for (int idx = tid; idx < WSTASH_U64; idx += NTHR) {
        int k = idx / 54, rem = idx % 54;
        int c = rem / 18, h = (rem % 18) / 9, t9 = rem % 9;
        int g = gq*GPER + k;
        int off = h ? 3 : 0;
        float w0 = conv_w[((2*g  )*6 + off + c)*9 + t9];
        float w1 = conv_w[((2*g+1)*6 + off + c)*9 + t9];
        swp[idx] = pack2(w0, w1);
    }
    mbar_wait(mbar_u32, 0);
    __syncthreads();              // images + stash visible

    // 2x2 output block coords: 16 x 24 blocks = 384 threads.
    const int by = tid / 24, bx = tid % 24;
    const int iy = 4*by,     ix = 4*bx;
    const bool right_edge = (bx == 23);
    const bool bot_edge   = (by == 15);
    const u64 ABSM = 0x7FFFFFFF7FFFFFFFull;
    const int lane = tid & 31, wid = tid >> 5;

    #pragma unroll 1
    for (int k = 0; k < GPER; k++) {
        const int g  = gq*GPER + k;
        const int c0 = 2*g, c1 = 2*g + 1;

        // accA[img][pos] = (A(c0), A(c1)); accB likewise. pos: tl,tr,bl,br
        u64 accA[5][4], accB[5][4];
        #pragma unroll
        for (int i = 0; i < 5; i++)
            #pragma unroll
            for (int p = 0; p < 4; p++) { accA[i][p] = 0ull; accB[i][p] = 0ull; }

        #pragma unroll
        for (int c = 0; c < 3; c++) {
            // per input-channel weights (broadcast LDS)
            u64 wA[9], wB[9];
            #pragma unroll
            for (int t = 0; t < 9; t++) {
                wA[t] = swp[((k*3 + c)*2 + 0)*9 + t];
                wB[t] = swp[((k*3 + c)*2 + 1)*9 + t];
            }
            #pragma unroll
            for (int i = 0; i < 5; i++) {
                const __nv_bfloat16* base = simg + (size_t)i*IMG_ELEMS
                                          + (c*HI + iy)*WI + ix;
                #pragma unroll
                for (int r = 0; r < 5; r++) {
                    u64 vv[5];
                    if (bot_edge && r == 4) {
                        #pragma unroll
                        for (int q = 0; q < 5; q++) vv[q] = 0ull;
                    } else {
                        const char* rp = (const char*)(base + r*WI);
                        uint2 u2 = *(const uint2*)rp;             // v0..v3
                        uint32_t u4 = *(const uint32_t*)(rp + 8); // v4,(v5)
                        vv[0] = dup_lo(u2.x);
                        vv[1] = dup_hi(u2.x);
                        vv[2] = dup_lo(u2.y);
                        vv[3] = dup_hi(u2.y);
                        vv[4] = right_edge ? 0ull : dup_lo(u4);
                    }
                    if (r < 3) {                   // top out-row, ky = r
                        #pragma unroll
                        for (int kx = 0; kx < 3; kx++) {
                            int t = r*3 + kx;
                            accA[i][0] = fma2(wA[t], vv[kx],   accA[i][0]);
                            accA[i][1] = fma2(wA[t], vv[kx+2], accA[i][1]);
                            accB[i][0] = fma2(wB[t], vv[kx],   accB[i][0]);
                            accB[i][1] = fma2(wB[t], vv[kx+2], accB[i][1]);
                        }
                    }
                    if (r >= 2) {                  // bottom out-row, ky = r-2
                        #pragma unroll
                        for (int kx = 0; kx < 3; kx++) {
                            int t = (r-2)*3 + kx;
                            accA[i][2] = fma2(wA[t], vv[kx],   accA[i][2]);
                            accA[i][3] = fma2(wA[t], vv[kx+2], accA[i][3]);
                            accB[i][2] = fma2(wB[t], vv[kx],   accB[i][2]);
                            accB[i][3] = fma2(wB[t], vv[kx+2], accB[i][3]);
                        }
                    }
                }
            }
        }

        // Fold bias into A accumulators.
        const u64 bias2 = pack2(__ldg(conv_b + c0), __ldg(conv_b + c1));
        #pragma unroll
        for (int i = 0; i < 5; i++)
            #pragma unroll
            for (int p = 0; p < 4; p++)
                accA[i][p] = add2(accA[i][p], bias2);

        // Combine directly from registers: accp[q] += (t + |t|),
        // t = A_i + B_j; relu(x) = (x+|x|)/2 exactly, 1/2 applied at store.
        u64 accp[25];
        #pragma unroll
        for (int q = 0; q < 25; q++) accp[q] = 0ull;
        #pragma unroll
        for (int p = 0; p < 4; p++)
            #pragma unroll
            for (int i = 0; i < 5; i++)
                #pragma unroll
                for (int j = 0; j < 5; j++) {
                    u64 t = add2(accA[i][p], accB[j][p]);
                    int q = i*5 + j;
                    accp[q] = add2(accp[q], t);
                    accp[q] = add2(accp[q], t & ABSM);
                }

        // Smem-transpose reduction: 3 phases of <=9 pair-columns.
        // Phase: all threads STS their packed partials; warp w (< nq) linearly
        // sums column w (12 LDS.64 + adds) then one short u64 shuffle tree.
        #pragma unroll
        for (int ph = 0; ph < 3; ph++) {
            const int q0 = ph*9;
            const int nq = (ph == 2) ? 7 : 9;
            #pragma unroll
            for (int qq = 0; qq < 9; qq++)
                if (qq < nq) rscr[qq*NTHR + tid] = accp[q0 + qq];
            __syncthreads();
            if (wid < nq) {
                u64 s = 0ull;
                #pragma unroll
                for (int t = 0; t < NTHR/32; t++)
                    s = add2(s, rscr[wid*NTHR + lane + t*32]);
                float2 f = unpack2(s);
                #pragma unroll
                for (int off = 16; off; off >>= 1) {
                    f.x += __shfl_xor_sync(0xFFFFFFFFu, f.x, off);
                    f.y += __shfl_xor_sync(0xFFFFFFFFu, f.y, off);
                }
                if (lane == 0) {
                    const int q = q0 + wid;
                    float* dst = S + ((size_t)z*NT + b*25 + q)*COUT;
                    dst[c0] = 0.5f * f.x;
                    dst[c1] = 0.5f * f.y;
                }
            }
            __syncthreads();
        }
    }
}

// ---------------------------------------------------------------------------
// logits over BOTH states (3200 tuples): warp per tuple.
// ---------------------------------------------------------------------------
__global__ __launch_bounds__(256)
void logits_kernel(const float* __restrict__ S,    // [3200][128]
                   const float* __restrict__ w2,   // [4][32]
                   const float* __restrict__ b2,   // [4]
                   const float* __restrict__ temp,
                   float* __restrict__ out)        // [3200][4]
{
    const int lane = threadIdx.x & 31;
    const int t = blockIdx.x * 8 + (threadIdx.x >> 5);
    if (t >= 2*NT) return;

    float s[4];
    #pragma unroll
    for (int p = 0; p < 4; p++)
        s[p] = S[(size_t)t*COUT + p*32 + lane] * w2[p*32 + lane];
    #pragma unroll
    for (int off = 16; off; off >>= 1)
        #pragma unroll
        for (int p = 0; p < 4; p++)
            s[p] += __shfl_xor_sync(0xFFFFFFFFu, s[p], off);

    if (lane < 4) {
        float invT = 1.0f / (*temp);
        float logit = s[lane] * (1.0f / (float)NPOS) + b2[lane];
        out[t*4 + lane] = 1.0f / (1.0f + expf(-logit * invT));
    }
}

// adj[b][t] = (t / 25 == b)
__global__ void adj_kernel(float* __restrict__ out)
{
    int idx = blockIdx.x * blockDim.x + threadIdx.x;
    if (idx >= NB * NT) return;
    int b = idx / NT;
    int t = idx % NT;
    out[idx] = (t / (NOBJ*NOBJ) == b) ? 1.0f : 0.0f;
}

// ---------------------------------------------------------------------------
extern "C" void kernel_launch(void* const* d_in, const int* in_sizes, int n_in,
                              void* d_out, int out_size)
{
    const float* state      = (const float*)d_in[0];
    const float* state_next = (const float*)d_in[1];
    const float* conv_w     = (const float*)d_in[2];
    const float* conv_b     = (const float*)d_in[3];
    const float* w2         = (const float*)d_in[4];
    const float* b2         = (const float*)d_in[5];
    // d_in[6] = n_obj (constant NOBJ), d_in[7] = temp
    const float* temp       = (const float*)d_in[7];
    float* out = (float*)d_out;

    __nv_bfloat16* imgs; cudaGetSymbolAddress((void**)&imgs, g_imgs);
    float* S;            cudaGetSymbolAddress((void**)&S, g_S);

    cudaFuncSetAttribute(fused_kernel, cudaFuncAttributeMaxDynamicSharedMemorySize,
                         SMEM_BYTES);

    // 1) convert both states' images to bf16
    cvt_kernel<<<(2*N4PS + 255)/256, 256>>>(state, state_next, imgs);

    // 2) persistent fused conv+combine: grid (gq, batch, state) = 1024 CTAs
    fused_kernel<<<dim3(GPER, NB, 2), NTHR, SMEM_BYTES>>>(imgs, conv_w, conv_b, S);

    // 3) logits for both states (out = preds | preds_next, contiguous)
    logits_kernel<<<(2*NT + 7)/8, 256>>>(S, w2, b2, temp, out);

    // 4) adjacency
    adj_kernel<<<(NB*NT + 255)/256, 256>>>(out + 2*NT*PP);
}